// round 1
// baseline (speedup 1.0000x reference)
#include <cuda_runtime.h>
#include <cuda_bf16.h>

// Transform matrix (top 3 rows x 4 cols, row-major), computed on device.
__device__ float g_mat[12];

__global__ void setup_matrix_kernel(const float* __restrict__ w,
                                    const float* __restrict__ v,
                                    const float* __restrict__ theta,
                                    const int* __restrict__ cam_idx) {
    int ci = cam_idx[0];
    float w0 = w[ci * 3 + 0], w1 = w[ci * 3 + 1], w2 = w[ci * 3 + 2];
    float v0 = v[ci * 3 + 0], v1 = v[ci * 3 + 1], v2 = v[ci * 3 + 2];
    float th = theta[ci];

    float s = sinf(th), c = cosf(th);
    float A = 1.0f - c;       // coefficient for K
    float B = th - s;         // coefficient for K^2 in V

    // K = skew(w)
    float K[3][3] = {
        {0.0f, -w2,  w1},
        { w2, 0.0f, -w0},
        {-w1,  w0, 0.0f}
    };
    // K2 = K @ K
    float K2[3][3];
    #pragma unroll
    for (int i = 0; i < 3; i++)
        #pragma unroll
        for (int j = 0; j < 3; j++)
            K2[i][j] = K[i][0] * K[0][j] + K[i][1] * K[1][j] + K[i][2] * K[2][j];

    // R = I + s*K + (1-c)*K2   ;   V = I*th + (1-c)*K + (th - s)*K2 ; t = V @ v
    float vin[3] = {v0, v1, v2};
    #pragma unroll
    for (int i = 0; i < 3; i++) {
        float t = 0.0f;
        #pragma unroll
        for (int j = 0; j < 3; j++) {
            float I = (i == j) ? 1.0f : 0.0f;
            float R = I + s * K[i][j] + A * K2[i][j];
            float V = I * th + A * K[i][j] + B * K2[i][j];
            g_mat[i * 4 + j] = R;
            t += V * vin[j];
        }
        g_mat[i * 4 + 3] = t;
    }
}

// Each thread handles 4 consecutive points via float4.
// x layout: row r at x + r*N. out same. Row 3 of out == row 3 of x.
__global__ void __launch_bounds__(256)
transform_kernel(const float4* __restrict__ x, float4* __restrict__ out, int n4) {
    int i = blockIdx.x * blockDim.x + threadIdx.x;
    if (i >= n4) return;

    // Broadcast loads of the matrix (uniform address -> cached).
    float m00 = g_mat[0],  m01 = g_mat[1],  m02 = g_mat[2],  m03 = g_mat[3];
    float m10 = g_mat[4],  m11 = g_mat[5],  m12 = g_mat[6],  m13 = g_mat[7];
    float m20 = g_mat[8],  m21 = g_mat[9],  m22 = g_mat[10], m23 = g_mat[11];

    float4 x0 = x[i];
    float4 x1 = x[i + n4];
    float4 x2 = x[i + 2 * n4];
    float4 x3 = x[i + 3 * n4];

    float4 o0, o1, o2;
    o0.x = m00 * x0.x + m01 * x1.x + m02 * x2.x + m03 * x3.x;
    o0.y = m00 * x0.y + m01 * x1.y + m02 * x2.y + m03 * x3.y;
    o0.z = m00 * x0.z + m01 * x1.z + m02 * x2.z + m03 * x3.z;
    o0.w = m00 * x0.w + m01 * x1.w + m02 * x2.w + m03 * x3.w;

    o1.x = m10 * x0.x + m11 * x1.x + m12 * x2.x + m13 * x3.x;
    o1.y = m10 * x0.y + m11 * x1.y + m12 * x2.y + m13 * x3.y;
    o1.z = m10 * x0.z + m11 * x1.z + m12 * x2.z + m13 * x3.z;
    o1.w = m10 * x0.w + m11 * x1.w + m12 * x2.w + m13 * x3.w;

    o2.x = m20 * x0.x + m21 * x1.x + m22 * x2.x + m23 * x3.x;
    o2.y = m20 * x0.y + m21 * x1.y + m22 * x2.y + m23 * x3.y;
    o2.z = m20 * x0.z + m21 * x1.z + m22 * x2.z + m23 * x3.z;
    o2.w = m20 * x0.w + m21 * x1.w + m22 * x2.w + m23 * x3.w;

    out[i]           = o0;
    out[i + n4]      = o1;
    out[i + 2 * n4]  = o2;
    out[i + 3 * n4]  = x3;   // bottom row [0,0,0,1] @ x == x[3]
}

extern "C" void kernel_launch(void* const* d_in, const int* in_sizes, int n_in,
                              void* d_out, int out_size) {
    const float* x     = (const float*)d_in[0];   // [4, N]
    const float* w     = (const float*)d_in[1];   // [16, 3]
    const float* v     = (const float*)d_in[2];   // [16, 3]
    const float* theta = (const float*)d_in[3];   // [16, 1]
    const int*   cam   = (const int*)d_in[4];     // scalar

    int N  = in_sizes[0] / 4;   // points per row
    int n4 = N / 4;             // float4 elements per row

    setup_matrix_kernel<<<1, 1>>>(w, v, theta, cam);

    int threads = 256;
    int blocks  = (n4 + threads - 1) / threads;
    transform_kernel<<<blocks, threads>>>((const float4*)x, (float4*)d_out, n4);
}

// round 2
// speedup vs baseline: 1.0152x; 1.0152x over previous
#include <cuda_runtime.h>
#include <cuda_bf16.h>

// Fused kernel: every thread computes the 3x4 SE(3) matrix from the scalar
// inputs (uniform-address broadcast loads, ~50 FLOPs — negligible vs 256MB of
// streaming), then transforms TWO float4 groups per row: index i and i + n4/2.
// Both halves are fully coalesced. 8 independent LDG.128 are issued up front
// for MLP=8 before any dependent FMA/store.
__global__ void __launch_bounds__(256)
transform_fused_kernel(const float4* __restrict__ x, float4* __restrict__ out,
                       const float* __restrict__ w, const float* __restrict__ v,
                       const float* __restrict__ theta, const int* __restrict__ cam,
                       int n4) {
    int half = n4 >> 1;
    int i = blockIdx.x * blockDim.x + threadIdx.x;
    if (i >= half) return;
    int j = i + half;

    // ---- Issue all 8 independent streaming loads first ----
    float4 a0 = x[i];
    float4 a1 = x[i + n4];
    float4 a2 = x[i + 2 * n4];
    float4 a3 = x[i + 3 * n4];
    float4 b0 = x[j];
    float4 b1 = x[j + n4];
    float4 b2 = x[j + 2 * n4];
    float4 b3 = x[j + 3 * n4];

    // ---- Compute the matrix while loads are in flight ----
    int ci = cam[0];
    float w0 = w[ci * 3 + 0], w1 = w[ci * 3 + 1], w2 = w[ci * 3 + 2];
    float v0 = v[ci * 3 + 0], v1 = v[ci * 3 + 1], v2 = v[ci * 3 + 2];
    float th = theta[ci];

    float s, c;
    __sincosf(th, &s, &c);
    // Use precise sin/cos to match reference within fp32 ULPs:
    s = sinf(th); c = cosf(th);
    float A = 1.0f - c;
    float B = th - s;

    // K = skew(w); K2 = K*K
    float K00 = 0.f, K01 = -w2, K02 = w1;
    float K10 = w2,  K11 = 0.f, K12 = -w0;
    float K20 = -w1, K21 = w0,  K22 = 0.f;

    float K2_00 = K00*K00 + K01*K10 + K02*K20;
    float K2_01 = K00*K01 + K01*K11 + K02*K21;
    float K2_02 = K00*K02 + K01*K12 + K02*K22;
    float K2_10 = K10*K00 + K11*K10 + K12*K20;
    float K2_11 = K10*K01 + K11*K11 + K12*K21;
    float K2_12 = K10*K02 + K11*K12 + K12*K22;
    float K2_20 = K20*K00 + K21*K10 + K22*K20;
    float K2_21 = K20*K01 + K21*K11 + K22*K21;
    float K2_22 = K20*K02 + K21*K12 + K22*K22;

    // R = I + s*K + A*K2
    float m00 = 1.0f + s*K00 + A*K2_00;
    float m01 =        s*K01 + A*K2_01;
    float m02 =        s*K02 + A*K2_02;
    float m10 =        s*K10 + A*K2_10;
    float m11 = 1.0f + s*K11 + A*K2_11;
    float m12 =        s*K12 + A*K2_12;
    float m20 =        s*K20 + A*K2_20;
    float m21 =        s*K21 + A*K2_21;
    float m22 = 1.0f + s*K22 + A*K2_22;

    // V = I*th + A*K + B*K2 ; t = V @ v
    float V00 = th + A*K00 + B*K2_00;
    float V01 =      A*K01 + B*K2_01;
    float V02 =      A*K02 + B*K2_02;
    float V10 =      A*K10 + B*K2_10;
    float V11 = th + A*K11 + B*K2_11;
    float V12 =      A*K12 + B*K2_12;
    float V20 =      A*K20 + B*K2_20;
    float V21 =      A*K21 + B*K2_21;
    float V22 = th + A*K22 + B*K2_22;

    float m03 = V00*v0 + V01*v1 + V02*v2;
    float m13 = V10*v0 + V11*v1 + V12*v2;
    float m23 = V20*v0 + V21*v1 + V22*v2;

    // ---- Transform group A ----
    float4 oa0, oa1, oa2;
    oa0.x = m00*a0.x + m01*a1.x + m02*a2.x + m03*a3.x;
    oa0.y = m00*a0.y + m01*a1.y + m02*a2.y + m03*a3.y;
    oa0.z = m00*a0.z + m01*a1.z + m02*a2.z + m03*a3.z;
    oa0.w = m00*a0.w + m01*a1.w + m02*a2.w + m03*a3.w;
    oa1.x = m10*a0.x + m11*a1.x + m12*a2.x + m13*a3.x;
    oa1.y = m10*a0.y + m11*a1.y + m12*a2.y + m13*a3.y;
    oa1.z = m10*a0.z + m11*a1.z + m12*a2.z + m13*a3.z;
    oa1.w = m10*a0.w + m11*a1.w + m12*a2.w + m13*a3.w;
    oa2.x = m20*a0.x + m21*a1.x + m22*a2.x + m23*a3.x;
    oa2.y = m20*a0.y + m21*a1.y + m22*a2.y + m23*a3.y;
    oa2.z = m20*a0.z + m21*a1.z + m22*a2.z + m23*a3.z;
    oa2.w = m20*a0.w + m21*a1.w + m22*a2.w + m23*a3.w;

    out[i]          = oa0;
    out[i + n4]     = oa1;
    out[i + 2 * n4] = oa2;
    out[i + 3 * n4] = a3;

    // ---- Transform group B ----
    float4 ob0, ob1, ob2;
    ob0.x = m00*b0.x + m01*b1.x + m02*b2.x + m03*b3.x;
    ob0.y = m00*b0.y + m01*b1.y + m02*b2.y + m03*b3.y;
    ob0.z = m00*b0.z + m01*b1.z + m02*b2.z + m03*b3.z;
    ob0.w = m00*b0.w + m01*b1.w + m02*b2.w + m03*b3.w;
    ob1.x = m10*b0.x + m11*b1.x + m12*b2.x + m13*b3.x;
    ob1.y = m10*b0.y + m11*b1.y + m12*b2.y + m13*b3.y;
    ob1.z = m10*b0.z + m11*b1.z + m12*b2.z + m13*b3.z;
    ob1.w = m10*b0.w + m11*b1.w + m12*b2.w + m13*b3.w;
    ob2.x = m20*b0.x + m21*b1.x + m22*b2.x + m23*b3.x;
    ob2.y = m20*b0.y + m21*b1.y + m22*b2.y + m23*b3.y;
    ob2.z = m20*b0.z + m21*b1.z + m22*b2.z + m23*b3.z;
    ob2.w = m20*b0.w + m21*b1.w + m22*b2.w + m23*b3.w;

    out[j]          = ob0;
    out[j + n4]     = ob1;
    out[j + 2 * n4] = ob2;
    out[j + 3 * n4] = b3;
}

extern "C" void kernel_launch(void* const* d_in, const int* in_sizes, int n_in,
                              void* d_out, int out_size) {
    const float* x     = (const float*)d_in[0];   // [4, N]
    const float* w     = (const float*)d_in[1];   // [16, 3]
    const float* v     = (const float*)d_in[2];   // [16, 3]
    const float* theta = (const float*)d_in[3];   // [16, 1]
    const int*   cam   = (const int*)d_in[4];     // scalar

    int N  = in_sizes[0] / 4;   // points per row
    int n4 = N / 4;             // float4 elements per row
    int half = n4 / 2;          // two groups per thread

    int threads = 256;
    int blocks  = (half + threads - 1) / threads;
    transform_fused_kernel<<<blocks, threads>>>(
        (const float4*)x, (float4*)d_out, w, v, theta, cam, n4);
}

// round 4
// speedup vs baseline: 1.0440x; 1.0284x over previous
#include <cuda_runtime.h>
#include <cuda_bf16.h>

// Fused single-kernel version: every thread computes the 3x4 SE(3) matrix from
// the scalar inputs (uniform broadcast loads, ~50 FLOPs), then transforms one
// float4 group per row. Streaming memory hints: __ldcs (evict-first) on the
// point loads, __stcs on the stores — data is touched exactly once, so keep it
// out of L2's allocation path.
__global__ void __launch_bounds__(256)
transform_fused_kernel(const float4* __restrict__ x, float4* __restrict__ out,
                       const float* __restrict__ w, const float* __restrict__ v,
                       const float* __restrict__ theta, const int* __restrict__ cam,
                       int n4) {
    int i = blockIdx.x * blockDim.x + threadIdx.x;
    if (i >= n4) return;

    // ---- Issue all 4 independent streaming loads first (evict-first) ----
    float4 x0 = __ldcs(x + i);
    float4 x1 = __ldcs(x + i + n4);
    float4 x2 = __ldcs(x + i + 2 * n4);
    float4 x3 = __ldcs(x + i + 3 * n4);

    // ---- Compute the matrix while loads are in flight ----
    int ci = cam[0];
    float w0 = w[ci * 3 + 0], w1 = w[ci * 3 + 1], w2 = w[ci * 3 + 2];
    float v0 = v[ci * 3 + 0], v1 = v[ci * 3 + 1], v2 = v[ci * 3 + 2];
    float th = theta[ci];

    float s = sinf(th), c = cosf(th);
    float A = 1.0f - c;
    float B = th - s;

    // K = skew(w); K2 = K*K
    float K01 = -w2, K02 = w1;
    float K10 = w2,  K12 = -w0;
    float K20 = -w1, K21 = w0;

    float K2_00 = K01*K10 + K02*K20;
    float K2_01 = K02*K21;
    float K2_02 = K01*K12;
    float K2_10 = K12*K20;
    float K2_11 = K10*K01 + K12*K21;
    float K2_12 = K10*K02;
    float K2_20 = K21*K10;
    float K2_21 = K20*K01;
    float K2_22 = K20*K02 + K21*K12;

    // R = I + s*K + A*K2
    float m00 = 1.0f + A*K2_00;
    float m01 =        s*K01 + A*K2_01;
    float m02 =        s*K02 + A*K2_02;
    float m10 =        s*K10 + A*K2_10;
    float m11 = 1.0f + A*K2_11;
    float m12 =        s*K12 + A*K2_12;
    float m20 =        s*K20 + A*K2_20;
    float m21 =        s*K21 + A*K2_21;
    float m22 = 1.0f + A*K2_22;

    // V = I*th + A*K + B*K2 ; t = V @ v
    float V00 = th + B*K2_00;
    float V01 =      A*K01 + B*K2_01;
    float V02 =      A*K02 + B*K2_02;
    float V10 =      A*K10 + B*K2_10;
    float V11 = th + B*K2_11;
    float V12 =      A*K12 + B*K2_12;
    float V20 =      A*K20 + B*K2_20;
    float V21 =      A*K21 + B*K2_21;
    float V22 = th + B*K2_22;

    float m03 = V00*v0 + V01*v1 + V02*v2;
    float m13 = V10*v0 + V11*v1 + V12*v2;
    float m23 = V20*v0 + V21*v1 + V22*v2;

    // ---- Transform ----
    float4 o0, o1, o2;
    o0.x = m00*x0.x + m01*x1.x + m02*x2.x + m03*x3.x;
    o0.y = m00*x0.y + m01*x1.y + m02*x2.y + m03*x3.y;
    o0.z = m00*x0.z + m01*x1.z + m02*x2.z + m03*x3.z;
    o0.w = m00*x0.w + m01*x1.w + m02*x2.w + m03*x3.w;

    o1.x = m10*x0.x + m11*x1.x + m12*x2.x + m13*x3.x;
    o1.y = m10*x0.y + m11*x1.y + m12*x2.y + m13*x3.y;
    o1.z = m10*x0.z + m11*x1.z + m12*x2.z + m13*x3.z;
    o1.w = m10*x0.w + m11*x1.w + m12*x2.w + m13*x3.w;

    o2.x = m20*x0.x + m21*x1.x + m22*x2.x + m23*x3.x;
    o2.y = m20*x0.y + m21*x1.y + m22*x2.y + m23*x3.y;
    o2.z = m20*x0.z + m21*x1.z + m22*x2.z + m23*x3.z;
    o2.w = m20*x0.w + m21*x1.w + m22*x2.w + m23*x3.w;

    // ---- Streaming stores ----
    __stcs(out + i,          o0);
    __stcs(out + i + n4,     o1);
    __stcs(out + i + 2 * n4, o2);
    __stcs(out + i + 3 * n4, x3);   // bottom row [0,0,0,1] @ x == x[3]
}

extern "C" void kernel_launch(void* const* d_in, const int* in_sizes, int n_in,
                              void* d_out, int out_size) {
    const float* x     = (const float*)d_in[0];   // [4, N]
    const float* w     = (const float*)d_in[1];   // [16, 3]
    const float* v     = (const float*)d_in[2];   // [16, 3]
    const float* theta = (const float*)d_in[3];   // [16, 1]
    const int*   cam   = (const int*)d_in[4];     // scalar

    int N  = in_sizes[0] / 4;   // points per row
    int n4 = N / 4;             // float4 elements per row

    int threads = 256;
    int blocks  = (n4 + threads - 1) / threads;
    transform_fused_kernel<<<blocks, threads>>>(
        (const float4*)x, (float4*)d_out, w, v, theta, cam, n4);
}

// round 5
// speedup vs baseline: 1.0455x; 1.0014x over previous
#include <cuda_runtime.h>
#include <cuda_bf16.h>

// Blackwell 256-bit vector load/store (sm_100a: ld/st.global.v8.f32).
__device__ __forceinline__ void ldg_v8(const float* __restrict__ p, float r[8]) {
    asm volatile("ld.global.v8.f32 {%0,%1,%2,%3,%4,%5,%6,%7}, [%8];"
                 : "=f"(r[0]), "=f"(r[1]), "=f"(r[2]), "=f"(r[3]),
                   "=f"(r[4]), "=f"(r[5]), "=f"(r[6]), "=f"(r[7])
                 : "l"(p));
}
__device__ __forceinline__ void stg_v8(float* __restrict__ p, const float r[8]) {
    asm volatile("st.global.v8.f32 [%0], {%1,%2,%3,%4,%5,%6,%7,%8};"
                 :: "l"(p),
                    "f"(r[0]), "f"(r[1]), "f"(r[2]), "f"(r[3]),
                    "f"(r[4]), "f"(r[5]), "f"(r[6]), "f"(r[7])
                 : "memory");
}

// Fused kernel: every thread computes the 3x4 SE(3) matrix from the scalar
// inputs (uniform broadcast loads), then transforms 8 consecutive points per
// row using 256-bit vector memory ops. 4 independent 256-bit loads are issued
// up front; the matrix math overlaps the load latency.
__global__ void __launch_bounds__(256)
transform_fused_kernel(const float* __restrict__ x, float* __restrict__ out,
                       const float* __restrict__ w, const float* __restrict__ v,
                       const float* __restrict__ theta, const int* __restrict__ cam,
                       int N) {
    long long base = (long long)(blockIdx.x * blockDim.x + threadIdx.x) * 8;
    if (base >= N) return;

    // ---- Issue 4 independent 256-bit streaming loads ----
    float x0[8], x1[8], x2[8], x3[8];
    ldg_v8(x + base,              x0);
    ldg_v8(x + base + (long long)N,     x1);
    ldg_v8(x + base + 2LL * N,    x2);
    ldg_v8(x + base + 3LL * N,    x3);

    // ---- Compute the matrix while loads are in flight ----
    int ci = cam[0];
    float w0 = w[ci * 3 + 0], w1 = w[ci * 3 + 1], w2 = w[ci * 3 + 2];
    float v0 = v[ci * 3 + 0], v1 = v[ci * 3 + 1], v2 = v[ci * 3 + 2];
    float th = theta[ci];

    float s = sinf(th), c = cosf(th);
    float A = 1.0f - c;
    float B = th - s;

    // K = skew(w); K2 = K*K (zero-diagonal terms folded out)
    float K01 = -w2, K02 = w1;
    float K10 = w2,  K12 = -w0;
    float K20 = -w1, K21 = w0;

    float K2_00 = K01*K10 + K02*K20;
    float K2_01 = K02*K21;
    float K2_02 = K01*K12;
    float K2_10 = K12*K20;
    float K2_11 = K10*K01 + K12*K21;
    float K2_12 = K10*K02;
    float K2_20 = K21*K10;
    float K2_21 = K20*K01;
    float K2_22 = K20*K02 + K21*K12;

    // R = I + s*K + A*K2
    float m00 = 1.0f + A*K2_00;
    float m01 =        s*K01 + A*K2_01;
    float m02 =        s*K02 + A*K2_02;
    float m10 =        s*K10 + A*K2_10;
    float m11 = 1.0f + A*K2_11;
    float m12 =        s*K12 + A*K2_12;
    float m20 =        s*K20 + A*K2_20;
    float m21 =        s*K21 + A*K2_21;
    float m22 = 1.0f + A*K2_22;

    // V = I*th + A*K + B*K2 ; t = V @ v
    float V00 = th + B*K2_00;
    float V01 =      A*K01 + B*K2_01;
    float V02 =      A*K02 + B*K2_02;
    float V10 =      A*K10 + B*K2_10;
    float V11 = th + B*K2_11;
    float V12 =      A*K12 + B*K2_12;
    float V20 =      A*K20 + B*K2_20;
    float V21 =      A*K21 + B*K2_21;
    float V22 = th + B*K2_22;

    float m03 = V00*v0 + V01*v1 + V02*v2;
    float m13 = V10*v0 + V11*v1 + V12*v2;
    float m23 = V20*v0 + V21*v1 + V22*v2;

    // ---- Transform 8 points ----
    float o0[8], o1[8], o2[8];
    #pragma unroll
    for (int k = 0; k < 8; k++) {
        o0[k] = m00*x0[k] + m01*x1[k] + m02*x2[k] + m03*x3[k];
        o1[k] = m10*x0[k] + m11*x1[k] + m12*x2[k] + m13*x3[k];
        o2[k] = m20*x0[k] + m21*x1[k] + m22*x2[k] + m23*x3[k];
    }

    // ---- 256-bit stores; bottom row [0,0,0,1] @ x == x[3] ----
    stg_v8(out + base,           o0);
    stg_v8(out + base + (long long)N,  o1);
    stg_v8(out + base + 2LL * N, o2);
    stg_v8(out + base + 3LL * N, x3);
}

extern "C" void kernel_launch(void* const* d_in, const int* in_sizes, int n_in,
                              void* d_out, int out_size) {
    const float* x     = (const float*)d_in[0];   // [4, N]
    const float* w     = (const float*)d_in[1];   // [16, 3]
    const float* v     = (const float*)d_in[2];   // [16, 3]
    const float* theta = (const float*)d_in[3];   // [16, 1]
    const int*   cam   = (const int*)d_in[4];     // scalar

    int N  = in_sizes[0] / 4;   // points per row (8388608)
    int n8 = N / 8;             // 8-float groups per row

    int threads = 256;
    int blocks  = (n8 + threads - 1) / threads;
    transform_fused_kernel<<<blocks, threads>>>(
        x, (float*)d_out, w, v, theta, cam, N);
}